// round 3
// baseline (speedup 1.0000x reference)
#include <cuda_runtime.h>
#include <math.h>

// Batched EKF split 3 ways: each segment's 6x6 filter factors exactly into
// three independent 2x2 filters (blocks {0,2},{1,3},{4,5}).  One thread per
// (segment, component): 3N threads = 768 warps (3x the warp count of the
// 1-thread-per-segment version) -> latency hiding across warps.
// Measurements staged into padded shared memory via coalesced float4 loads.
// Fused deterministic grid reduction (last-block pattern).

#define SEGS_PER_BLOCK 32
#define THREADS 96          // 3 warps: warp0=comp A, warp1=comp B, warp2=comp C

__device__ float g_partials[1024];
__device__ int   g_count = 0;

__device__ __forceinline__ float tanh_fast(float x){ float y; asm("tanh.approx.f32 %0, %1;" : "=f"(y) : "f"(x)); return y; }
__device__ __forceinline__ float rcp_fast (float x){ float y; asm("rcp.approx.f32 %0, %1;"  : "=f"(y) : "f"(x)); return y; }
__device__ __forceinline__ float lg2_fast (float x){ float y; asm("lg2.approx.f32 %0, %1;"  : "=f"(y) : "f"(x)); return y; }

__global__ void __launch_bounds__(THREADS) ekf_kernel(
    const float* __restrict__ params,
    const float* __restrict__ cp,
    const float* __restrict__ init_state,
    const float* __restrict__ meas,
    float* __restrict__ out,
    int N, int T)
{
    const float DT    = 1.0f / 120.0f;
    const float GRAV  = 9.81f;
    const float KS    = 100.0f;
    const float WRAP  = 4.71238898038469f;   // 1.5*pi
    const float TWOPI = 6.283185307179586f;
    const float LN2   = 0.6931471805599453f;

    const float fric = fabsf(params[0]);
    const float damp = fabsf(params[1]);

    const float fg    = fric * GRAV;
    const float cF    = 1.0f - DT * damp;
    const float DTfgk = DT * fg * KS;

    extern __shared__ float sm[];            // [SEGS_PER_BLOCK][3T+1] padded rows
    const int ROW = 3 * T + 1;               // odd for T even -> conflict-free LDS

    int tid  = threadIdx.x;
    int comp = tid >> 5;                     // 0,1,2  (warp-uniform)
    int s    = tid & 31;                     // segment within block
    int segBase = blockIdx.x * SEGS_PER_BLOCK;
    int n = segBase + s;

    // ---- cooperative coalesced staging: 32 segments x 3T floats ----
    {
        int totalF4 = (SEGS_PER_BLOCK * 3 * T) >> 2;      // e.g. 1536
        int validF4 = 0;
        if (segBase < N) {
            int validSegs = N - segBase; if (validSegs > SEGS_PER_BLOCK) validSegs = SEGS_PER_BLOCK;
            validF4 = (validSegs * 3 * T) >> 2;
        }
        const float4* mp4 = (const float4*)(meas + (size_t)segBase * 3 * T);
        int per = 3 * T >> 2;                              // float4s per segment row (48)
        for (int f = tid; f < totalF4; f += THREADS) {
            if (f < validF4) {
                float4 v = mp4[f];
                int seg = f / per;
                int off = (f - seg * per) << 2;
                float* dst = sm + seg * ROW + off;
                dst[0] = v.x; dst[1] = v.y; dst[2] = v.z; dst[3] = v.w;
            }
        }
    }
    __syncthreads();

    float acc_l2 = 0.0f;     // sum of lg2(s_t) for this component
    float acc_m  = 0.0f;     // sum of y^2 / s_t

    if (n < N) {
        // component scalar constants
        float Rc, Qx, Qv;
        {
            float r = (comp == 0) ? cp[0] : (comp == 1) ? cp[1] : cp[2];
            Rc = expf(r);
            Qx = expf((comp < 2) ? cp[3] : cp[5]);
            Qv = expf((comp < 2) ? cp[4] : cp[6]);
        }
        int xi = (comp < 2) ? comp : 4;
        float x = init_state[n*6 + xi];
        float v = init_state[n*6 + xi + ((comp < 2) ? 2 : 1)];

        float p00 = 0.01f, p01 = 0.0f, p11 = 0.01f;
        const float* zr = sm + s * ROW + comp;   // z at step t: zr[3*t]

        const float cF2 = cF * cF;
        int G = T >> 2;

        if (comp < 2) {
            // ---- nonlinear blocks (friction tanh) ----
            for (int g = 0; g < G; g++) {
                const float* zb = zr + g * 12;
                float z0 = zb[0], z1 = zb[3], z2 = zb[6], z3 = zb[9];
                float sprod = 1.0f;
                #pragma unroll
                for (int i = 0; i < 4; i++) {
                    float z = (i==0)?z0:(i==1)?z1:(i==2)?z2:z3;
                    float th  = tanh_fast(KS * v);
                    float xp  = fmaf(DT, v, x);
                    float vp  = fmaf(-DT, fmaf(fg, th, damp * v), v);
                    float a   = fmaf(-DTfgk, fmaf(-th, th, 1.0f), cF);
                    float Pp00 = fmaf(DT, fmaf(DT, p11, p01 + p01), p00) + Qx;
                    float Pp01 = a * fmaf(DT, p11, p01);
                    float Pp11 = fmaf(a * a, p11, Qv);
                    float y  = z - xp;
                    float S  = Pp00 + Rc;
                    float iS = rcp_fast(S);
                    float k0 = Pp00 * iS, k1 = Pp01 * iS;
                    x = fmaf(k0, y, xp);  v = fmaf(k1, y, vp);
                    float om = 1.0f - k0;
                    p00 = Pp00 * om; p01 = Pp01 * om;
                    p11 = fmaf(-k1, Pp01, Pp11);
                    acc_m = fmaf(y * y, iS, acc_m);
                    sprod *= S;
                }
                acc_l2 += lg2_fast(sprod);
            }
        } else {
            // ---- linear block (theta/omega) with angle wrap ----
            for (int g = 0; g < G; g++) {
                const float* zb = zr + g * 12;
                float z0 = zb[0], z1 = zb[3], z2 = zb[6], z3 = zb[9];
                float sprod = 1.0f;
                #pragma unroll
                for (int i = 0; i < 4; i++) {
                    float z = (i==0)?z0:(i==1)?z1:(i==2)?z2:z3;
                    float xp  = fmaf(DT, v, x);
                    float vp  = cF * v;
                    float Pp00 = fmaf(DT, fmaf(DT, p11, p01 + p01), p00) + Qx;
                    float Pp01 = cF * fmaf(DT, p11, p01);
                    float Pp11 = fmaf(cF2, p11, Qv);
                    float y = z - xp;
                    if      (y >  WRAP) y -= TWOPI;
                    else if (y < -WRAP) y += TWOPI;
                    float S  = Pp00 + Rc;
                    float iS = rcp_fast(S);
                    float k0 = Pp00 * iS, k1 = Pp01 * iS;
                    x = fmaf(k0, y, xp);  v = fmaf(k1, y, vp);
                    float om = 1.0f - k0;
                    p00 = Pp00 * om; p01 = Pp01 * om;
                    p11 = fmaf(-k1, Pp01, Pp11);
                    acc_m = fmaf(y * y, iS, acc_m);
                    sprod *= S;
                }
                acc_l2 += lg2_fast(sprod);
            }
        }
    }

    float loss = 0.5f * fmaf(LN2, acc_l2, acc_m);

    // ---- deterministic block reduction: warp trees + 3 leaders ----
    __shared__ float red[3];
    #pragma unroll
    for (int o = 16; o > 0; o >>= 1)
        loss += __shfl_down_sync(0xffffffffu, loss, o);
    if ((tid & 31) == 0) red[comp] = loss;
    __syncthreads();

    if (tid == 0) {
        float blocksum = red[0] + red[1] + red[2];
        g_partials[blockIdx.x] = blocksum;
    }
    __threadfence();

    // last-block final reduction (warp 0 only)
    __shared__ int s_last;
    if (tid == 0) {
        int old = atomicAdd(&g_count, 1);
        s_last = (old == (int)gridDim.x - 1);
    }
    __syncthreads();
    if (s_last && tid < 32) {
        __threadfence();
        int nb = gridDim.x;
        float acc = 0.0f;
        for (int j = tid; j < nb; j += 32)
            acc += g_partials[j];
        #pragma unroll
        for (int o = 16; o > 0; o >>= 1)
            acc += __shfl_down_sync(0xffffffffu, acc, o);
        if (tid == 0) {
            out[0] = acc / (float)N;
            g_count = 0;      // reset for next graph replay
        }
    }
}

extern "C" void kernel_launch(void* const* d_in, const int* in_sizes, int n_in,
                              void* d_out, int out_size)
{
    const float* params = (const float*)d_in[0];
    const float* cp     = (const float*)d_in[1];
    const float* x0     = (const float*)d_in[2];
    const float* meas   = (const float*)d_in[3];
    float* out = (float*)d_out;

    int N = in_sizes[2] / 6;
    int T = in_sizes[3] / (N * 3);
    int nblocks = (N + SEGS_PER_BLOCK - 1) / SEGS_PER_BLOCK;
    size_t smem = (size_t)SEGS_PER_BLOCK * (3 * T + 1) * sizeof(float);

    ekf_kernel<<<nblocks, THREADS, smem>>>(params, cp, x0, meas, out, N, T);
}